// round 14
// baseline (speedup 1.0000x reference)
#include <cuda_runtime.h>
#include <cuda_fp16.h>
#include <cstdint>

#define M_DIM 1024
#define N_DIM 512
#define K_DIM 512

#define BM 64
#define BN 32
#define KC 64
#define NCHUNK (K_DIM / KC)    // 8
#define NTHREADS 256

// per-chunk layout: A 8KB (64 rows x 128B) | B 4KB (32 rows x 128B)
#define A_OFF 0
#define B_OFF 8192
#define CHUNK_BYTES 12288
#define SMEM_DYN (NCHUNK * CHUNK_BYTES)   // 96KB -> 2 CTAs/SM

// ---------------- helpers ----------------
__device__ __forceinline__ uint32_t smem_u32(const void* p) {
    uint32_t a;
    asm("{ .reg .u64 t; cvta.to.shared.u64 t, %1; cvt.u32.u64 %0, t; }"
        : "=r"(a) : "l"(p));
    return a;
}
__device__ __forceinline__ uint32_t sw128(uint32_t off) {
    return off ^ ((off >> 3) & 0x70);
}
__device__ __forceinline__ void ldsm4(uint32_t* r, uint32_t addr) {
    asm volatile("ldmatrix.sync.aligned.m8n8.x4.shared.b16 {%0,%1,%2,%3}, [%4];"
                 : "=r"(r[0]), "=r"(r[1]), "=r"(r[2]), "=r"(r[3]) : "r"(addr));
}
__device__ __forceinline__ void mma_f16(float* c, const uint32_t* a, const uint32_t* b) {
    asm volatile(
        "mma.sync.aligned.m16n8k16.row.col.f32.f16.f16.f32 "
        "{%0,%1,%2,%3}, {%4,%5,%6,%7}, {%8,%9}, {%0,%1,%2,%3};"
        : "+f"(c[0]), "+f"(c[1]), "+f"(c[2]), "+f"(c[3])
        : "r"(a[0]), "r"(a[1]), "r"(a[2]), "r"(a[3]), "r"(b[0]), "r"(b[1]));
}
__device__ __forceinline__ uint32_t pack_hi(float a, float b) {
    __half2 h = __halves2half2(__float2half_rn(a), __float2half_rn(b));
    return *reinterpret_cast<uint32_t*>(&h);
}

// ---------------- fused kernel ----------------
__global__ __launch_bounds__(NTHREADS, 2)
void filp_kernel(const float* __restrict__ X,
                 const float* __restrict__ W,
                 const float* __restrict__ bias,
                 float* __restrict__ out)
{
    extern __shared__ char smem[];
    const uint32_t sbase = smem_u32(smem);

    const int tid  = threadIdx.x;
    const int lane = tid & 31;
    const int wid  = tid >> 5;            // 0..7
    const int wm   = (wid & 3) * 16;      // warp M offset (4 groups)
    const int wn   = (wid >> 2) * 16;     // warp N offset (2 groups)

    const int m0 = blockIdx.y * BM;
    const int n0 = blockIdx.x * BN;

    // bias prefetch
    float2 bb[2];
    #pragma unroll
    for (int nt = 0; nt < 2; nt++)
        bb[nt] = *reinterpret_cast<const float2*>(
            bias + n0 + wn + nt * 8 + (lane & 3) * 2);

    // even/odd k accumulators
    float acc[2][2][4];
    #pragma unroll
    for (int p = 0; p < 2; p++)
        #pragma unroll
        for (int b = 0; b < 2; b++)
            #pragma unroll
            for (int q = 0; q < 4; q++) acc[p][b][q] = 0.0f;

    const int arow_l  = lane & 15;
    const int ahalf16 = ((lane >> 4) & 1) * 16;
    const int brow_l  = (lane & 7) + ((lane & 16) ? 8 : 0);
    const int bhalf16 = ((lane >> 3) & 1) * 16;

    uint32_t fa[2][4], fb[2][4];

    auto load_frags = [&](int ks, int pb) {
        const uint32_t stb = sbase + (uint32_t)(ks >> 2) * CHUNK_BYTES;
        const int sub = ks & 3;
        const uint32_t kb_a = (uint32_t)(sub * 32 + ahalf16);
        const uint32_t kb_b = (uint32_t)(sub * 32 + bhalf16);
        const uint32_t ra = (uint32_t)(wm + arow_l);
        ldsm4(fa[pb], stb + A_OFF + ra * 128 + (kb_a ^ ((ra & 7) << 4)));
        const uint32_t rb = (uint32_t)(wn + brow_l);
        ldsm4(fb[pb], stb + B_OFF + rb * 128 + (kb_b ^ ((rb & 7) << 4)));
    };

    // per chunk: A 1024 + B 512 = 1536 float4 units; 6 per thread
    auto ldg_chunk = [&](int c, float4* v) {
        const int kc = c * KC;
        #pragma unroll
        for (int i = 0; i < 6; i++) {
            int u = i * NTHREADS + tid;     // 0..1535
            if (u < 1024) {
                int r  = u >> 4;
                int cu = u & 15;
                v[i] = *reinterpret_cast<const float4*>(
                    X + (size_t)(m0 + r) * K_DIM + kc + cu * 4);
            } else {
                int t  = u - 1024;
                int r  = t >> 4;
                int cu = t & 15;
                v[i] = *reinterpret_cast<const float4*>(
                    W + (size_t)(n0 + r) * K_DIM + kc + cu * 4);
            }
        }
    };
    auto sts_chunk = [&](int c, const float4* v) {
        const int base = c * CHUNK_BYTES;
        #pragma unroll
        for (int i = 0; i < 6; i++) {
            int u = i * NTHREADS + tid;
            uint2 hi;
            hi.x = pack_hi(v[i].x, v[i].y);
            hi.y = pack_hi(v[i].z, v[i].w);
            if (u < 1024) {
                int r  = u >> 4;
                int cu = u & 15;
                uint32_t off = sw128((uint32_t)(r * 128 + cu * 8));
                *reinterpret_cast<uint2*>(&smem[base + A_OFF + off]) = hi;
            } else {
                int t  = u - 1024;
                int r  = t >> 4;
                int cu = t & 15;
                uint32_t off = sw128((uint32_t)(r * 128 + cu * 8));
                *reinterpret_cast<uint2*>(&smem[base + B_OFF + off]) = hi;
            }
        }
    };

    // ---- stage whole K (no intermediate barriers) ----
    float4 vreg[2][6];
    ldg_chunk(0, vreg[0]);
    #pragma unroll
    for (int c = 0; c < NCHUNK; c++) {
        if (c + 1 < NCHUNK) ldg_chunk(c + 1, vreg[(c + 1) & 1]);
        sts_chunk(c, vreg[c & 1]);
    }
    __syncthreads();   // the ONLY barrier

    // ---- 32 k-steps straight through ----
    load_frags(0, 0);
    #pragma unroll
    for (int ks = 0; ks < 32; ks++) {
        const int cur = ks & 1;
        if (ks < 31) load_frags(ks + 1, cur ^ 1);
        mma_f16(acc[cur][0], fa[cur], &fb[cur][0]);
        mma_f16(acc[cur][1], fa[cur], &fb[cur][2]);
    }

    // ---- fused epilogue: out = x * wx + bias ; x from resident A tile ----
    // X[m][n] == A_smem[m-m0][k=n]; n = n0+cn, chunk = n>>6, col = (n0&63)+cn
    const uint32_t achunk = sbase + (uint32_t)(n0 >> 6) * CHUNK_BYTES + A_OFF;
    const int ncol0 = (n0 & 63);
    #pragma unroll
    for (int nt = 0; nt < 2; nt++) {
        const int rm = wm + (lane >> 2);
        const int cn = wn + nt * 8 + (lane & 3) * 2;
        const int n  = n0 + cn;
        uint32_t xa0, xa1;
        asm volatile("ld.shared.b32 %0, [%1];" : "=r"(xa0)
                     : "r"(achunk + sw128((uint32_t)(rm * 128 + (ncol0 + cn) * 2))));
        asm volatile("ld.shared.b32 %0, [%1];" : "=r"(xa1)
                     : "r"(achunk + sw128((uint32_t)((rm + 8) * 128 + (ncol0 + cn) * 2))));
        float2 x0 = __half22float2(*reinterpret_cast<__half2*>(&xa0));
        float2 x1 = __half22float2(*reinterpret_cast<__half2*>(&xa1));

        float wx0 = acc[0][nt][0] + acc[1][nt][0];
        float wx1 = acc[0][nt][1] + acc[1][nt][1];
        float wx2 = acc[0][nt][2] + acc[1][nt][2];
        float wx3 = acc[0][nt][3] + acc[1][nt][3];

        float2 o0, o1;
        o0.x = fmaf(x0.x, wx0, bb[nt].x);
        o0.y = fmaf(x0.y, wx1, bb[nt].y);
        o1.x = fmaf(x1.x, wx2, bb[nt].x);
        o1.y = fmaf(x1.y, wx3, bb[nt].y);
        *reinterpret_cast<float2*>(out + (size_t)(m0 + rm) * N_DIM + n) = o0;
        *reinterpret_cast<float2*>(out + (size_t)(m0 + rm + 8) * N_DIM + n) = o1;
    }
}

// ---------------- launch ----------------
extern "C" void kernel_launch(void* const* d_in, const int* in_sizes, int n_in,
                              void* d_out, int out_size) {
    const float* x    = (const float*)d_in[0];   // (1024, 512)
    const float* w    = (const float*)d_in[1];   // (512, 512)
    const float* bias = (const float*)d_in[2];   // (512,)
    float* out        = (float*)d_out;           // (1024, 512)

    cudaFuncSetAttribute(filp_kernel, cudaFuncAttributeMaxDynamicSharedMemorySize, SMEM_DYN);

    dim3 grid(N_DIM / BN, M_DIM / BM);   // (16, 16) = 256 CTAs, 2 per SM
    filp_kernel<<<grid, NTHREADS, SMEM_DYN>>>(x, w, bias, out);
}

// round 15
// speedup vs baseline: 1.1026x; 1.1026x over previous
#include <cuda_runtime.h>
#include <cuda_fp16.h>
#include <cstdint>

#define M_DIM 1024
#define N_DIM 512
#define K_DIM 512

#define BM 64
#define BN 64
#define KC 64
#define NCHUNK (K_DIM / KC)    // 8
#define NTHREADS 512           // 8 consumer + 8 producer warps

#define A_OFF 0
#define B_OFF 8192
#define CHUNK_BYTES 16384
#define SMEM_DYN (NCHUNK * CHUNK_BYTES)   // 128KB, whole K resident

// ---------------- helpers ----------------
__device__ __forceinline__ uint32_t smem_u32(const void* p) {
    uint32_t a;
    asm("{ .reg .u64 t; cvta.to.shared.u64 t, %1; cvt.u32.u64 %0, t; }"
        : "=r"(a) : "l"(p));
    return a;
}
__device__ __forceinline__ uint32_t sw128(uint32_t off) {
    return off ^ ((off >> 3) & 0x70);
}
__device__ __forceinline__ void ldsm4(uint32_t* r, uint32_t addr) {
    asm volatile("ldmatrix.sync.aligned.m8n8.x4.shared.b16 {%0,%1,%2,%3}, [%4];"
                 : "=r"(r[0]), "=r"(r[1]), "=r"(r[2]), "=r"(r[3]) : "r"(addr));
}
__device__ __forceinline__ void mma_f16(float* c, const uint32_t* a, const uint32_t* b) {
    asm volatile(
        "mma.sync.aligned.m16n8k16.row.col.f32.f16.f16.f32 "
        "{%0,%1,%2,%3}, {%4,%5,%6,%7}, {%8,%9}, {%0,%1,%2,%3};"
        : "+f"(c[0]), "+f"(c[1]), "+f"(c[2]), "+f"(c[3])
        : "r"(a[0]), "r"(a[1]), "r"(a[2]), "r"(a[3]), "r"(b[0]), "r"(b[1]));
}
__device__ __forceinline__ uint32_t pack_hi(float a, float b) {
    __half2 h = __halves2half2(__float2half_rn(a), __float2half_rn(b));
    return *reinterpret_cast<uint32_t*>(&h);
}
// named barrier: chunk c uses id 1+c, count = all 512 threads
__device__ __forceinline__ void bar_arrive(int id) {
    asm volatile("bar.arrive %0, %1;" :: "r"(id), "r"(NTHREADS));
}
__device__ __forceinline__ void bar_wait(int id) {
    asm volatile("bar.sync %0, %1;" :: "r"(id), "r"(NTHREADS) : "memory");
}

// ---------------- fused warp-specialized kernel ----------------
__global__ __launch_bounds__(NTHREADS, 1)
void filp_kernel(const float* __restrict__ X,
                 const float* __restrict__ W,
                 const float* __restrict__ bias,
                 float* __restrict__ out)
{
    extern __shared__ char smem[];
    const uint32_t sbase = smem_u32(smem);

    const int tid  = threadIdx.x;
    const int lane = tid & 31;
    const int wid  = tid >> 5;           // 0..15

    const int m0 = blockIdx.y * BM;
    const int n0 = blockIdx.x * BN;

    if (wid >= 8) {
        // ================= PRODUCERS (warps 8..15, 256 threads) =============
        const int ptid = tid - 256;

        // mapping: 2048 float4 units/chunk (A 1024 | B 1024), 8 per thread
        auto ldg_chunk = [&](int c, float4* v) {
            const int kc = c * KC;
            #pragma unroll
            for (int i = 0; i < 8; i++) {
                int u = i * 256 + ptid;       // 0..2047
                int r  = (u >> 4) & 63;
                int cu = u & 15;
                if (u < 1024)
                    v[i] = *reinterpret_cast<const float4*>(
                        X + (size_t)(m0 + r) * K_DIM + kc + cu * 4);
                else
                    v[i] = *reinterpret_cast<const float4*>(
                        W + (size_t)(n0 + r) * K_DIM + kc + cu * 4);
            }
        };
        auto sts_chunk = [&](int c, const float4* v) {
            const int base = c * CHUNK_BYTES;
            #pragma unroll
            for (int i = 0; i < 8; i++) {
                int u = i * 256 + ptid;
                int r  = (u >> 4) & 63;
                int cu = u & 15;
                uint32_t off = sw128((uint32_t)(r * 128 + cu * 8));
                uint2 hi;
                hi.x = pack_hi(v[i].x, v[i].y);
                hi.y = pack_hi(v[i].z, v[i].w);
                if (u < 1024)
                    *reinterpret_cast<uint2*>(&smem[base + A_OFF + off]) = hi;
                else
                    *reinterpret_cast<uint2*>(&smem[base + B_OFF + off]) = hi;
            }
        };

        float4 v[2][8];
        ldg_chunk(0, v[0]);
        #pragma unroll
        for (int c = 0; c < NCHUNK; c++) {
            if (c + 1 < NCHUNK) ldg_chunk(c + 1, v[(c + 1) & 1]);
            sts_chunk(c, v[c & 1]);
            asm volatile("membar.cta;" ::: "memory");
            bar_arrive(1 + c);                 // signal chunk c ready
        }
        // producers done; exit
    } else {
        // ================= CONSUMERS (warps 0..7, 256 threads) ==============
        const int wm = (wid & 3) * 16;       // 4 m-groups of 16
        const int wn = (wid >> 2) * 32;      // 2 n-groups of 32

        // bias prefetch (early, long before use)
        float2 bb[4];
        #pragma unroll
        for (int nti = 0; nti < 4; nti++)
            bb[nti] = *reinterpret_cast<const float2*>(
                bias + n0 + wn + nti * 8 + (lane & 3) * 2);

        // even/odd-k accumulators: acc[p][nti][q]
        float acc[2][4][4];
        #pragma unroll
        for (int p = 0; p < 2; p++)
            #pragma unroll
            for (int nti = 0; nti < 4; nti++)
                #pragma unroll
                for (int q = 0; q < 4; q++) acc[p][nti][q] = 0.0f;

        const int arow_l  = lane & 15;
        const int ahalf16 = ((lane >> 4) & 1) * 16;
        const int brow_l  = (lane & 7) + ((lane & 16) ? 8 : 0);
        const int bhalf16 = ((lane >> 3) & 1) * 16;

        uint32_t fa[2][4], fb[2][2][4];

        auto load_frags = [&](int ks, int pb) {
            const uint32_t stb = sbase + (uint32_t)(ks >> 2) * CHUNK_BYTES;
            const int sub = ks & 3;
            const uint32_t kb_a = (uint32_t)(sub * 32 + ahalf16);
            const uint32_t kb_b = (uint32_t)(sub * 32 + bhalf16);
            const uint32_t ra = (uint32_t)(wm + arow_l);
            ldsm4(fa[pb], stb + A_OFF + ra * 128 + (kb_a ^ ((ra & 7) << 4)));
            const uint32_t rb0 = (uint32_t)(wn + brow_l);
            ldsm4(fb[pb][0], stb + B_OFF + rb0 * 128 + (kb_b ^ ((rb0 & 7) << 4)));
            const uint32_t rb1 = (uint32_t)(wn + 16 + brow_l);
            ldsm4(fb[pb][1], stb + B_OFF + rb1 * 128 + (kb_b ^ ((rb1 & 7) << 4)));
        };

        #pragma unroll
        for (int c = 0; c < NCHUNK; c++) {
            bar_wait(1 + c);                  // wait for chunk c staged
            load_frags(c * 4, 0);
            #pragma unroll
            for (int s = 0; s < 4; s++) {
                const int ks  = c * 4 + s;
                const int cur = s & 1;
                if (s < 3) load_frags(ks + 1, cur ^ 1);
                const int p = ks & 1;
                mma_f16(acc[p][0], fa[cur], &fb[cur][0][0]);
                mma_f16(acc[p][1], fa[cur], &fb[cur][0][2]);
                mma_f16(acc[p][2], fa[cur], &fb[cur][1][0]);
                mma_f16(acc[p][3], fa[cur], &fb[cur][1][2]);
            }
        }

        // ---- fused epilogue: out = x * wx + bias ; x from resident A tile
        // X[m][n] == A_smem[m-m0][k=n]  (n-range inside resident k-range)
        const uint32_t achunk = sbase + (uint32_t)(n0 / KC) * CHUNK_BYTES + A_OFF;
        const int rm = wm + (lane >> 2);
        #pragma unroll
        for (int nti = 0; nti < 4; nti++) {
            const int cn = wn + nti * 8 + (lane & 3) * 2;
            const int n  = n0 + cn;
            uint32_t xa0, xa1;
            asm volatile("ld.shared.b32 %0, [%1];" : "=r"(xa0)
                         : "r"(achunk + sw128((uint32_t)(rm * 128 + cn * 2))));
            asm volatile("ld.shared.b32 %0, [%1];" : "=r"(xa1)
                         : "r"(achunk + sw128((uint32_t)((rm + 8) * 128 + cn * 2))));
            float2 x0 = __half22float2(*reinterpret_cast<__half2*>(&xa0));
            float2 x1 = __half22float2(*reinterpret_cast<__half2*>(&xa1));

            float wx0 = acc[0][nti][0] + acc[1][nti][0];
            float wx1 = acc[0][nti][1] + acc[1][nti][1];
            float wx2 = acc[0][nti][2] + acc[1][nti][2];
            float wx3 = acc[0][nti][3] + acc[1][nti][3];

            float2 o0, o1;
            o0.x = fmaf(x0.x, wx0, bb[nti].x);
            o0.y = fmaf(x0.y, wx1, bb[nti].y);
            o1.x = fmaf(x1.x, wx2, bb[nti].x);
            o1.y = fmaf(x1.y, wx3, bb[nti].y);
            *reinterpret_cast<float2*>(out + (size_t)(m0 + rm) * N_DIM + n) = o0;
            *reinterpret_cast<float2*>(out + (size_t)(m0 + rm + 8) * N_DIM + n) = o1;
        }
    }
}

// ---------------- launch ----------------
extern "C" void kernel_launch(void* const* d_in, const int* in_sizes, int n_in,
                              void* d_out, int out_size) {
    const float* x    = (const float*)d_in[0];   // (1024, 512)
    const float* w    = (const float*)d_in[1];   // (512, 512)
    const float* bias = (const float*)d_in[2];   // (512,)
    float* out        = (float*)d_out;           // (1024, 512)

    cudaFuncSetAttribute(filp_kernel, cudaFuncAttributeMaxDynamicSharedMemorySize, SMEM_DYN);

    dim3 grid(N_DIM / BN, M_DIM / BM);   // (8, 16) = 128 CTAs
    filp_kernel<<<grid, NTHREADS, SMEM_DYN>>>(x, w, bias, out);
}